// round 11
// baseline (speedup 1.0000x reference)
#include <cuda_runtime.h>
#include <cuda_bf16.h>

// WeightedAverage: out = sum_{3x3} v*exp(-v) / sum_{3x3} exp(-v)
// (softmax(-(local - x^2)) == softmax(-local): x^2 constant over patch axis;
//  zero padding contributes w=1 to denom, 0 to numer == loading v=0 OOB.)
//
// 8 columns per lane (2x LDG.128): halves per-byte issue overhead vs R8/R10
// (halo LDGs, loop/store/recurrence ops; exps 1.5 -> 1.25 per pixel).
// Block = 128 threads = 4 warps; warp sweeps 32 rows of a 256-col band ->
// tile 256x128. 1152 tiles, grid = 576 = exactly 2 tiles/block, single wave.
// Ring of 3 slots {2x float4, vl, vr}, vector+halo prefetched 2 rows ahead
// (R8). Sweep fully unrolled (R6: partial unroll kills MLP). Regs left loose
// (R9: capping regs re-serializes the prefetch).

#define IMG_W   1536
#define IMG_H   1536
#define SROWS   32
#define WPB     4
#define TILES_X 6
#define TILES_Y 12
#define N_IMG   16
#define N_TILES (TILES_X * TILES_Y * N_IMG)   // 1152
#define NBLK    576                           // 2 tiles per block

struct Slot { float4 a, b; float vl, vr; };
struct Pair { float4 a, b; };

__device__ __forceinline__ Pair padd(const Pair& x, const Pair& y) {
    Pair r;
    r.a = make_float4(x.a.x + y.a.x, x.a.y + y.a.y, x.a.z + y.a.z, x.a.w + y.a.w);
    r.b = make_float4(x.b.x + y.b.x, x.b.y + y.b.y, x.b.z + y.b.z, x.b.w + y.b.w);
    return r;
}

__global__ __launch_bounds__(128, 4)
void wavg_kernel(const float* __restrict__ x, float* __restrict__ out) {
    const int lane = threadIdx.x & 31;
    const int wrp  = threadIdx.x >> 5;

    #pragma unroll 1
    for (int t = blockIdx.x; t < N_TILES; t += NBLK) {
        const int img_i = t / (TILES_X * TILES_Y);
        const int rem   = t - img_i * (TILES_X * TILES_Y);
        const int ty    = rem / TILES_X;
        const int tx    = rem - ty * TILES_X;

        const int col0 = tx * 256 + lane * 8;
        const int y0   = ty * (WPB * SROWS) + wrp * SROWS;
        const size_t ibase = (size_t)img_i * (size_t)(IMG_W * IMG_H);
        const float* __restrict__ img = x + ibase;
        float* __restrict__ optr = out + ibase + (size_t)y0 * IMG_W + col0;

        const bool has_l = (col0 > 0);
        const bool has_r = (col0 + 8 < IMG_W);

        Slot ring[3];

        // Load row y: two float4s plus both halo scalars, together.
        auto loadrow = [&](int y) -> Slot {
            Slot s;
            s.a = make_float4(0.f, 0.f, 0.f, 0.f);
            s.b = make_float4(0.f, 0.f, 0.f, 0.f);
            s.vl = 0.f; s.vr = 0.f;
            if ((unsigned)y < (unsigned)IMG_H) {
                const float* p = img + (size_t)y * IMG_W + col0;
                s.a = __ldg(reinterpret_cast<const float4*>(p));
                s.b = __ldg(reinterpret_cast<const float4*>(p + 4));
                if (has_l) s.vl = __ldg(p - 1);
                if (has_r) s.vr = __ldg(p + 8);
            }
            return s;
        };

        // Horizontal 3-sums of w=exp(-v) and wv for one row (pure compute).
        auto hsum = [&](const Slot& s, Pair& w, Pair& wv) {
            const float w0 = __expf(-s.a.x);
            const float w1 = __expf(-s.a.y);
            const float w2 = __expf(-s.a.z);
            const float w3 = __expf(-s.a.w);
            const float w4 = __expf(-s.b.x);
            const float w5 = __expf(-s.b.y);
            const float w6 = __expf(-s.b.z);
            const float w7 = __expf(-s.b.w);
            const float wl = __expf(-s.vl);
            const float wr = __expf(-s.vr);
            w.a.x = wl + w0 + w1;
            w.a.y = w0 + w1 + w2;
            w.a.z = w1 + w2 + w3;
            w.a.w = w2 + w3 + w4;
            w.b.x = w3 + w4 + w5;
            w.b.y = w4 + w5 + w6;
            w.b.z = w5 + w6 + w7;
            w.b.w = w6 + w7 + wr;
            const float al = wl * s.vl;
            const float a0 = w0 * s.a.x, a1 = w1 * s.a.y;
            const float a2 = w2 * s.a.z, a3 = w3 * s.a.w;
            const float a4 = w4 * s.b.x, a5 = w5 * s.b.y;
            const float a6 = w6 * s.b.z, a7 = w7 * s.b.w;
            const float ar = wr * s.vr;
            wv.a.x = al + a0 + a1;
            wv.a.y = a0 + a1 + a2;
            wv.a.z = a1 + a2 + a3;
            wv.a.w = a2 + a3 + a4;
            wv.b.x = a3 + a4 + a5;
            wv.b.y = a4 + a5 + a6;
            wv.b.z = a5 + a6 + a7;
            wv.b.w = a6 + a7 + ar;
        };

        // Prologue. slot(row) = (row - y0 + 2) % 3.
        Slot s_m1 = loadrow(y0 - 1);
        Slot s_0  = loadrow(y0);
        ring[0] = loadrow(y0 + 1);
        ring[1] = loadrow(y0 + 2);

        Pair hw0, hv0, hw1, hv1;
        hsum(s_m1, hw0, hv0);
        hsum(s_0,  hw1, hv1);
        Pair Aw  = padd(hw0, hw1), Bw  = hw1;   // A = h(-1)+h(0), B = h(0)
        Pair Awv = padd(hv0, hv1), Bwv = hv1;

        #pragma unroll
        for (int k = 0; k < SROWS; k++) {
            // Prefetch row y0+k+3 into slot (k+2)%3.
            if (k < SROWS - 2)
                ring[(k + 2) % 3] = loadrow(y0 + k + 3);
            // Consume row y0+k+1 (slot k%3), loaded 2 iterations ago.
            Pair hw, hv;
            hsum(ring[k % 3], hw, hv);

            const Pair den = padd(Aw,  hw);
            const Pair num = padd(Awv, hv);
            float4 oa, ob;
            oa.x = __fdividef(num.a.x, den.a.x);
            oa.y = __fdividef(num.a.y, den.a.y);
            oa.z = __fdividef(num.a.z, den.a.z);
            oa.w = __fdividef(num.a.w, den.a.w);
            ob.x = __fdividef(num.b.x, den.b.x);
            ob.y = __fdividef(num.b.y, den.b.y);
            ob.z = __fdividef(num.b.z, den.b.z);
            ob.w = __fdividef(num.b.w, den.b.w);
            __stcs(reinterpret_cast<float4*>(optr),     oa);
            __stcs(reinterpret_cast<float4*>(optr + 4), ob);
            optr += IMG_W;

            Aw  = padd(Bw,  hw);  Bw  = hw;
            Awv = padd(Bwv, hv);  Bwv = hv;
        }
    }
}

extern "C" void kernel_launch(void* const* d_in, const int* in_sizes, int n_in,
                              void* d_out, int out_size) {
    const float* x = (const float*)d_in[0];
    float* out = (float*)d_out;
    wavg_kernel<<<NBLK, WPB * 32>>>(x, out);
}